// round 4
// baseline (speedup 1.0000x reference)
#include <cuda_runtime.h>

#define DINL static __device__ __forceinline__

// ------------------------------ scratch (static __device__, no allocs) -----
__device__ __align__(16) float g_xs0[512 * 1024];
__device__ __align__(16) float g_xs1[512 * 1024];
__device__ __align__(16) float g_pre[512 * 4096];
__device__ __align__(16) float g_hE[2][2][512];        // [dir][parity][j]
__device__ __align__(16) float g_hdec[2][2][1024];     // [layer][parity][j]
__device__ __align__(16) float g_cdec[2048];           // [layer*1024 + j]
__device__ __align__(16) float g_logits[32000];
__device__ __align__(16) float g_prob[512u * 32000u];  // [s][v] un-normalized exp
__device__ float g_psum[512 * 128];                    // per-step per-block partial sums
__device__ float g_sums[512];
__device__ unsigned long long g_packed[512];           // per-step argmax/max packed
__device__ unsigned g_cnt[4 * 32];                     // padded barrier counters
__device__ unsigned g_gen[4 * 32];

// ------------------------------ helpers ------------------------------------
DINL void gsync(int grp, unsigned nb) {
    __syncthreads();
    if (threadIdx.x == 0) {
        __threadfence();
        volatile unsigned* pg = &g_gen[grp * 32];
        unsigned gen = *pg;
        if (atomicAdd(&g_cnt[grp * 32], 1u) == nb - 1u) {
            atomicExch(&g_cnt[grp * 32], 0u);
            __threadfence();
            atomicExch(&g_gen[grp * 32], gen + 1u);
        } else {
            while (*pg == gen) { }
        }
        __threadfence();
    }
    __syncthreads();
}

DINL float wredsum(float v) {
#pragma unroll
    for (int o = 16; o > 0; o >>= 1) v += __shfl_xor_sync(0xFFFFFFFFu, v, o);
    return v;
}

DINL float sigm(float x) { return 1.0f / (1.0f + __expf(-x)); }

DINL float4 ldcg4(const float* p) { return __ldcg((const float4*)p); }
DINL float4 ldcs4(const float* p) { return __ldcs((const float4*)p); }
DINL float dot4(float4 a, float4 b) { return a.x * b.x + a.y * b.y + a.z * b.z + a.w * b.w; }

// ------------------------------ setup kernels ------------------------------
__global__ void zero_kernel() {
    int i = threadIdx.x;
    if (i < 512) g_packed[i] = 0ULL;
}

__global__ void embed_kernel(const int* __restrict__ x, const float* __restrict__ emb) {
    int t = blockIdx.x;
    int tok = x[t];
    const float4* src = (const float4*)(emb + (size_t)tok * 1024);
    float4* dst = (float4*)(g_xs0 + (size_t)t * 1024);
    dst[threadIdx.x] = src[threadIdx.x];  // 256 threads x float4 = 1024 floats
}

// ------------------------------ encoder input GEMM -------------------------
// C[t][n] = sum_k A[t][k] * B[n][k] + bias[n];  A:[512,1024] B:[4096,1024] C=g_pre
__global__ __launch_bounds__(256) void gemm_pre_kernel(int src, const float* __restrict__ B,
                                                       const float* __restrict__ bias) {
    const float* A = src ? g_xs1 : g_xs0;
    const int K = 1024, N = 4096;
    __shared__ float As[16][128];
    __shared__ float Bs[16][128];
    int bm = blockIdx.y * 128, bn = blockIdx.x * 128;
    int tid = threadIdx.x;
    int tx = tid & 15, ty = tid >> 4;
    float acc[8][8];
#pragma unroll
    for (int i = 0; i < 8; i++)
#pragma unroll
        for (int j = 0; j < 8; j++) acc[i][j] = 0.0f;

    int lr = tid >> 2;         // 0..63
    int lc = (tid & 3) * 4;    // 0,4,8,12

    for (int kt = 0; kt < K; kt += 16) {
#pragma unroll
        for (int h = 0; h < 2; h++) {
            int r = lr + h * 64;
            float4 a4 = *(const float4*)&A[(size_t)(bm + r) * K + kt + lc];
            As[lc + 0][r] = a4.x; As[lc + 1][r] = a4.y;
            As[lc + 2][r] = a4.z; As[lc + 3][r] = a4.w;
            float4 b4 = *(const float4*)&B[(size_t)(bn + r) * K + kt + lc];
            Bs[lc + 0][r] = b4.x; Bs[lc + 1][r] = b4.y;
            Bs[lc + 2][r] = b4.z; Bs[lc + 3][r] = b4.w;
        }
        __syncthreads();
#pragma unroll
        for (int k = 0; k < 16; k++) {
            float ar[8], br[8];
            *(float4*)&ar[0] = *(const float4*)&As[k][ty * 8];
            *(float4*)&ar[4] = *(const float4*)&As[k][ty * 8 + 4];
            *(float4*)&br[0] = *(const float4*)&Bs[k][tx * 8];
            *(float4*)&br[4] = *(const float4*)&Bs[k][tx * 8 + 4];
#pragma unroll
            for (int i = 0; i < 8; i++)
#pragma unroll
                for (int j = 0; j < 8; j++) acc[i][j] += ar[i] * br[j];
        }
        __syncthreads();
    }

    float bv[8];
#pragma unroll
    for (int j = 0; j < 8; j++) bv[j] = bias[bn + tx * 8 + j];
#pragma unroll
    for (int i = 0; i < 8; i++) {
        float* Cp = g_pre + (size_t)(bm + ty * 8 + i) * N + bn + tx * 8;
#pragma unroll
        for (int j = 0; j < 8; j += 4) {
            float4 o;
            o.x = acc[i][j + 0] + bv[j + 0];
            o.y = acc[i][j + 1] + bv[j + 1];
            o.z = acc[i][j + 2] + bv[j + 2];
            o.w = acc[i][j + 3] + bv[j + 3];
            *(float4*)(Cp + j) = o;
        }
    }
}

// ------------------------------ encoder recurrence -------------------------
// 128 blocks: blocks 0-63 forward dir, 64-127 backward dir. warp-per-j (512 j's/dir).
__global__ __launch_bounds__(256) void enc_rec_kernel(const float* __restrict__ Whh,
                                                      int layer) {
    int tid = threadIdx.x, lane = tid & 31, wid = tid >> 5;
    int grp = blockIdx.x >> 6;                    // 0=fwd 1=bwd
    int j = ((blockIdx.x & 63) << 3) + wid;       // 0..511
    const float* W = Whh + (size_t)grp * 2048 * 512;
    float* xs_next = (layer == 0) ? g_xs1 : g_xs0;

    float c = 0.0f;
    if (lane == 0) g_hE[grp][0][j] = 0.0f;
    gsync(grp, 64);

    const float* W0 = W + (size_t)(j) * 512;
    const float* W1 = W + (size_t)(512 + j) * 512;
    const float* W2 = W + (size_t)(1024 + j) * 512;
    const float* W3 = W + (size_t)(1536 + j) * 512;

    for (int it = 0; it < 512; it++) {
        int t = grp ? (511 - it) : it;
        int pin = it & 1, pout = pin ^ 1;
        const float* h = g_hE[grp][pin];
        float a0 = 0, a1 = 0, a2 = 0, a3 = 0;
#pragma unroll
        for (int kk = 0; kk < 4; kk++) {
            int k = kk * 128 + lane * 4;
            float4 hv = ldcg4(h + k);
            a0 += dot4(*(const float4*)(W0 + k), hv);
            a1 += dot4(*(const float4*)(W1 + k), hv);
            a2 += dot4(*(const float4*)(W2 + k), hv);
            a3 += dot4(*(const float4*)(W3 + k), hv);
        }
        a0 = wredsum(a0); a1 = wredsum(a1); a2 = wredsum(a2); a3 = wredsum(a3);
        if (lane == 0) {
            const float* pre = g_pre + (size_t)t * 4096 + grp * 2048;
            float gi = a0 + pre[j];
            float gf = a1 + pre[512 + j];
            float gg = a2 + pre[1024 + j];
            float go = a3 + pre[1536 + j];
            float iv = sigm(gi), fv = sigm(gf), gv = tanhf(gg), ov = sigm(go);
            c = fv * c + iv * gv;
            float hn = ov * tanhf(c);
            g_hE[grp][pout][j] = hn;
            xs_next[(size_t)t * 1024 + grp * 512 + j] = hn;
            if (it == 511) {
                g_hdec[layer][0][grp * 512 + j] = hn;  // parity-0 = decoder init
                g_cdec[layer * 1024 + grp * 512 + j] = c;
            }
        }
        gsync(grp, 64);
    }
}

// ------------------------------ decoder LSTM cell phase --------------------
template <bool XCG>
DINL void dec_lstm_phase(const float* x, const float* h,
                         const float* __restrict__ wi, const float* __restrict__ wh,
                         const float* __restrict__ bb, int j, int lane,
                         float& c, float* hout) {
    const float* wi0 = wi + (size_t)(j) * 1024;
    const float* wi1 = wi + (size_t)(1024 + j) * 1024;
    const float* wi2 = wi + (size_t)(2048 + j) * 1024;
    const float* wi3 = wi + (size_t)(3072 + j) * 1024;
    const float* wh0 = wh + (size_t)(j) * 1024;
    const float* wh1 = wh + (size_t)(1024 + j) * 1024;
    const float* wh2 = wh + (size_t)(2048 + j) * 1024;
    const float* wh3 = wh + (size_t)(3072 + j) * 1024;
    float a0 = 0, a1 = 0, a2 = 0, a3 = 0;
#pragma unroll
    for (int kk = 0; kk < 8; kk++) {
        int k = kk * 128 + lane * 4;
        float4 xv = XCG ? ldcg4(x + k) : *(const float4*)(x + k);
        float4 hv = ldcg4(h + k);
        a0 += dot4(*(const float4*)(wi0 + k), xv) + dot4(*(const float4*)(wh0 + k), hv);
        a1 += dot4(*(const float4*)(wi1 + k), xv) + dot4(*(const float4*)(wh1 + k), hv);
        a2 += dot4(*(const float4*)(wi2 + k), xv) + dot4(*(const float4*)(wh2 + k), hv);
        a3 += dot4(*(const float4*)(wi3 + k), xv) + dot4(*(const float4*)(wh3 + k), hv);
    }
    a0 = wredsum(a0); a1 = wredsum(a1); a2 = wredsum(a2); a3 = wredsum(a3);
    if (lane == 0) {
        float gi = a0 + bb[j], gf = a1 + bb[1024 + j];
        float gg = a2 + bb[2048 + j], go = a3 + bb[3072 + j];
        float iv = sigm(gi), fv = sigm(gf), gv = tanhf(gg), ov = sigm(go);
        c = fv * c + iv * gv;
        hout[j] = ov * tanhf(c);
    }
}

// ------------------------------ decoder (persistent, 128 blocks) ----------
__global__ __launch_bounds__(256) void decoder_kernel(
    const float* __restrict__ dec_emb, const float* __restrict__ Wih,
    const float* __restrict__ Whh, const float* __restrict__ bias,
    const float* __restrict__ clfW, const float* __restrict__ clfb) {
    int tid = threadIdx.x, lane = tid & 31, wid = tid >> 5;
    int gw = blockIdx.x * 8 + wid;  // 0..1023 == j
    int j = gw;
    __shared__ float sred[8];

    float c0 = g_cdec[j];
    float c1 = g_cdec[1024 + j];
    unsigned tok = 1u;  // START_IDX

    const float* Wih1 = Wih + (size_t)4096 * 1024;
    const float* Whh1 = Whh + (size_t)4096 * 1024;
    const float* b0 = bias;
    const float* b1 = bias + 4096;

    for (int s = 0; s < 512; s++) {
        int pin = s & 1, pout = pin ^ 1;

        // ---- P1: layer 0  (x = embedding row, read via L1 ok) ----
        dec_lstm_phase<false>(dec_emb + (size_t)tok * 1024, g_hdec[0][pin],
                              Wih, Whh, b0, j, lane, c0, g_hdec[0][pout]);
        gsync(2, 128);

        // ---- P2: layer 1  (x = h0 just written by other blocks -> ldcg) ----
        dec_lstm_phase<true>(g_hdec[0][pout], g_hdec[1][pin],
                             Wih1, Whh1, b1, j, lane, c1, g_hdec[1][pout]);
        gsync(2, 128);

        // ---- P3: classifier logits + packed argmax ----
        // 4 vocab rows per warp per iteration -> 32 in-flight 128B loads/warp
        // so the 131MB clf_W sweep is bandwidth-bound, not latency-bound.
        {
            const float* h1 = g_hdec[1][pout];
            float4 hr[8];
#pragma unroll
            for (int kk = 0; kk < 8; kk++) hr[kk] = ldcg4(h1 + kk * 128 + lane * 4);
            unsigned long long best = 0ULL;
#pragma unroll 1
            for (int v0 = gw; v0 < 32000; v0 += 4096) {
                // rows v0 + r*1024, clamped to stay in-bounds (result discarded)
                const float* wp[4];
                bool valid[4];
#pragma unroll
                for (int r = 0; r < 4; r++) {
                    int v = v0 + r * 1024;
                    valid[r] = (v < 32000);
                    wp[r] = clfW + (size_t)(valid[r] ? v : 31999) * 1024 + lane * 4;
                }
                float4 w[4][8];
#pragma unroll
                for (int r = 0; r < 4; r++)
#pragma unroll
                    for (int kk = 0; kk < 8; kk++) w[r][kk] = ldcs4(wp[r] + kk * 128);
                float a[4] = {0, 0, 0, 0};
#pragma unroll
                for (int r = 0; r < 4; r++)
#pragma unroll
                    for (int kk = 0; kk < 8; kk++) a[r] += dot4(w[r][kk], hr[kk]);
#pragma unroll
                for (int r = 0; r < 4; r++) {
                    float av = wredsum(a[r]);
                    int v = v0 + r * 1024;
                    if (lane == 0 && valid[r]) {
                        av += clfb[v];
                        g_logits[v] = av;
                        unsigned u = __float_as_uint(av);
                        u = (u & 0x80000000u) ? ~u : (u | 0x80000000u);
                        unsigned long long p =
                            ((unsigned long long)u << 32) |
                            (unsigned long long)(0xFFFFFFFFu - (unsigned)v);
                        if (p > best) best = p;
                    }
                }
            }
            if (lane == 0) atomicMax(&g_packed[s], best);
        }
        gsync(2, 128);

        // ---- P4: exp / partial sums / next token (no barrier; next-step
        //      barriers cover the logits-overwrite hazard) ----
        {
            unsigned long long gp = *(volatile unsigned long long*)&g_packed[s];
            unsigned hu = (unsigned)(gp >> 32);
            float gmax = __uint_as_float((hu & 0x80000000u) ? (hu & 0x7FFFFFFFu) : ~hu);
            tok = 0xFFFFFFFFu - (unsigned)(gp & 0xFFFFFFFFu);

            float lsum = 0.0f;
            int gt = blockIdx.x * 256 + tid;  // 0..32767, single element each
            if (gt < 32000) {
                float e = __expf(__ldcg(&g_logits[gt]) - gmax);
                __stcs(&g_prob[(size_t)s * 32000 + gt], e);
                lsum = e;
            }
            lsum = wredsum(lsum);
            if (lane == 0) sred[wid] = lsum;
            __syncthreads();
            if (tid < 32) {
                float v2 = (lane < 8) ? sred[lane] : 0.0f;
                v2 += __shfl_xor_sync(0xFFFFFFFFu, v2, 4);
                v2 += __shfl_xor_sync(0xFFFFFFFFu, v2, 2);
                v2 += __shfl_xor_sync(0xFFFFFFFFu, v2, 1);
                if (lane == 0) g_psum[s * 128 + blockIdx.x] = v2;
            }
        }
    }
}

// ------------------------------ deterministic softmax sums -----------------
__global__ void sums_kernel() {
    int s = blockIdx.x;
    int lane = threadIdx.x & 31, wid = threadIdx.x >> 5;
    float v = g_psum[s * 128 + threadIdx.x];
    v = wredsum(v);
    __shared__ float sr[4];
    if (lane == 0) sr[wid] = v;
    __syncthreads();
    if (threadIdx.x == 0) g_sums[s] = (sr[0] + sr[1]) + (sr[2] + sr[3]);
}

// ------------------------------ normalize + transpose to [V,T] -------------
__global__ void norm_tr_kernel(float* __restrict__ out) {
    __shared__ float tile[32][33];
    int v0 = blockIdx.x * 32, s0 = blockIdx.y * 32;
    int tx = threadIdx.x, ty = threadIdx.y;  // 32 x 8
#pragma unroll
    for (int i = 0; i < 32; i += 8)
        tile[ty + i][tx] = g_prob[(size_t)(s0 + ty + i) * 32000 + v0 + tx];
    __syncthreads();
    float rs = 1.0f / g_sums[s0 + tx];
#pragma unroll
    for (int i = 0; i < 32; i += 8)
        out[(size_t)(v0 + ty + i) * 512 + s0 + tx] = tile[tx][ty + i] * rs;
}

// ------------------------------ launch --------------------------------------
extern "C" void kernel_launch(void* const* d_in, const int* in_sizes, int n_in,
                              void* d_out, int out_size) {
    const int*   x       = (const int*)d_in[0];
    const float* enc_emb = (const float*)d_in[1];
    const float* enc_Wih = (const float*)d_in[2];
    const float* enc_Whh = (const float*)d_in[3];
    const float* enc_b   = (const float*)d_in[4];
    const float* dec_emb = (const float*)d_in[5];
    const float* dec_Wih = (const float*)d_in[6];
    const float* dec_Whh = (const float*)d_in[7];
    const float* dec_b   = (const float*)d_in[8];
    const float* clf_W   = (const float*)d_in[9];
    const float* clf_b   = (const float*)d_in[10];
    float* out = (float*)d_out;

    zero_kernel<<<1, 512>>>();
    embed_kernel<<<512, 256>>>(x, enc_emb);

    // encoder layer 0
    gemm_pre_kernel<<<dim3(32, 4), 256>>>(0, enc_Wih, enc_b);
    enc_rec_kernel<<<128, 256>>>(enc_Whh, 0);

    // encoder layer 1
    gemm_pre_kernel<<<dim3(32, 4), 256>>>(1, enc_Wih + (size_t)2 * 2048 * 1024,
                                          enc_b + 2 * 2048);
    enc_rec_kernel<<<128, 256>>>(enc_Whh + (size_t)2 * 2048 * 512, 1);

    // decoder (persistent, 512 greedy steps)
    decoder_kernel<<<128, 256>>>(dec_emb, dec_Wih, dec_Whh, dec_b, clf_W, clf_b);

    // softmax denominators + [V,T] output
    sums_kernel<<<512, 128>>>();
    norm_tr_kernel<<<dim3(1000, 16), dim3(32, 8)>>>(out);
}

// round 5
// speedup vs baseline: 1.9343x; 1.9343x over previous
#include <cuda_runtime.h>

#define DINL static __device__ __forceinline__

// ------------------------------ scratch (static __device__, no allocs) -----
__device__ __align__(16) float g_xs0[512 * 1024];
__device__ __align__(16) float g_xs1[512 * 1024];
__device__ __align__(16) float g_pre[512 * 4096];
__device__ __align__(16) float g_hE[2][2][512];        // [dir][parity][j]
__device__ __align__(16) float g_hdec[2][2][1024];     // [layer][parity][j]
__device__ __align__(16) float g_cdec[2048];           // [layer*1024 + j]
__device__ __align__(16) float g_logits[32000];
__device__ __align__(16) float g_prob[512u * 32000u];  // [s][v] un-normalized exp
__device__ float g_psum[512 * 128];                    // per-step per-block partial sums
__device__ float g_sums[512];
__device__ unsigned long long g_packed[512];           // per-step argmax/max packed
__device__ unsigned g_cnt[4 * 32];                     // padded barrier counters
__device__ unsigned g_gen[4 * 32];

// ------------------------------ helpers ------------------------------------
DINL void gsync(int grp, unsigned nb) {
    __syncthreads();
    if (threadIdx.x == 0) {
        __threadfence();
        volatile unsigned* pg = &g_gen[grp * 32];
        unsigned gen = *pg;
        if (atomicAdd(&g_cnt[grp * 32], 1u) == nb - 1u) {
            atomicExch(&g_cnt[grp * 32], 0u);
            __threadfence();
            atomicExch(&g_gen[grp * 32], gen + 1u);
        } else {
            while (*pg == gen) { }
        }
        __threadfence();
    }
    __syncthreads();
}

DINL float wredsum(float v) {
#pragma unroll
    for (int o = 16; o > 0; o >>= 1) v += __shfl_xor_sync(0xFFFFFFFFu, v, o);
    return v;
}

DINL float sigm(float x) { return 1.0f / (1.0f + __expf(-x)); }

DINL float4 ldcg4(const float* p) { return __ldcg((const float4*)p); }
DINL float4 ldcs4(const float* p) { return __ldcs((const float4*)p); }
DINL float dot4(float4 a, float4 b) { return a.x * b.x + a.y * b.y + a.z * b.z + a.w * b.w; }

// ------------------------------ setup kernels ------------------------------
__global__ void zero_kernel() {
    int i = threadIdx.x;
    if (i < 512) g_packed[i] = 0ULL;
}

__global__ void embed_kernel(const int* __restrict__ x, const float* __restrict__ emb) {
    int t = blockIdx.x;
    int tok = x[t];
    const float4* src = (const float4*)(emb + (size_t)tok * 1024);
    float4* dst = (float4*)(g_xs0 + (size_t)t * 1024);
    dst[threadIdx.x] = src[threadIdx.x];  // 256 threads x float4 = 1024 floats
}

// ------------------------------ encoder input GEMM -------------------------
// C[t][n] = sum_k A[t][k] * B[n][k] + bias[n];  A:[512,1024] B:[4096,1024] C=g_pre
__global__ __launch_bounds__(256) void gemm_pre_kernel(int src, const float* __restrict__ B,
                                                       const float* __restrict__ bias) {
    const float* A = src ? g_xs1 : g_xs0;
    const int K = 1024, N = 4096;
    __shared__ float As[16][128];
    __shared__ float Bs[16][128];
    int bm = blockIdx.y * 128, bn = blockIdx.x * 128;
    int tid = threadIdx.x;
    int tx = tid & 15, ty = tid >> 4;
    float acc[8][8];
#pragma unroll
    for (int i = 0; i < 8; i++)
#pragma unroll
        for (int j = 0; j < 8; j++) acc[i][j] = 0.0f;

    int lr = tid >> 2;         // 0..63
    int lc = (tid & 3) * 4;    // 0,4,8,12

    for (int kt = 0; kt < K; kt += 16) {
#pragma unroll
        for (int h = 0; h < 2; h++) {
            int r = lr + h * 64;
            float4 a4 = *(const float4*)&A[(size_t)(bm + r) * K + kt + lc];
            As[lc + 0][r] = a4.x; As[lc + 1][r] = a4.y;
            As[lc + 2][r] = a4.z; As[lc + 3][r] = a4.w;
            float4 b4 = *(const float4*)&B[(size_t)(bn + r) * K + kt + lc];
            Bs[lc + 0][r] = b4.x; Bs[lc + 1][r] = b4.y;
            Bs[lc + 2][r] = b4.z; Bs[lc + 3][r] = b4.w;
        }
        __syncthreads();
#pragma unroll
        for (int k = 0; k < 16; k++) {
            float ar[8], br[8];
            *(float4*)&ar[0] = *(const float4*)&As[k][ty * 8];
            *(float4*)&ar[4] = *(const float4*)&As[k][ty * 8 + 4];
            *(float4*)&br[0] = *(const float4*)&Bs[k][tx * 8];
            *(float4*)&br[4] = *(const float4*)&Bs[k][tx * 8 + 4];
#pragma unroll
            for (int i = 0; i < 8; i++)
#pragma unroll
                for (int j = 0; j < 8; j++) acc[i][j] += ar[i] * br[j];
        }
        __syncthreads();
    }

    float bv[8];
#pragma unroll
    for (int j = 0; j < 8; j++) bv[j] = bias[bn + tx * 8 + j];
#pragma unroll
    for (int i = 0; i < 8; i++) {
        float* Cp = g_pre + (size_t)(bm + ty * 8 + i) * N + bn + tx * 8;
#pragma unroll
        for (int j = 0; j < 8; j += 4) {
            float4 o;
            o.x = acc[i][j + 0] + bv[j + 0];
            o.y = acc[i][j + 1] + bv[j + 1];
            o.z = acc[i][j + 2] + bv[j + 2];
            o.w = acc[i][j + 3] + bv[j + 3];
            *(float4*)(Cp + j) = o;
        }
    }
}

// ------------------------------ encoder recurrence -------------------------
// 128 blocks: blocks 0-63 forward dir, 64-127 backward dir. warp-per-j (512 j's/dir).
__global__ __launch_bounds__(256) void enc_rec_kernel(const float* __restrict__ Whh,
                                                      int layer) {
    int tid = threadIdx.x, lane = tid & 31, wid = tid >> 5;
    int grp = blockIdx.x >> 6;                    // 0=fwd 1=bwd
    int j = ((blockIdx.x & 63) << 3) + wid;       // 0..511
    const float* W = Whh + (size_t)grp * 2048 * 512;
    float* xs_next = (layer == 0) ? g_xs1 : g_xs0;

    float c = 0.0f;
    if (lane == 0) g_hE[grp][0][j] = 0.0f;
    gsync(grp, 64);

    const float* W0 = W + (size_t)(j) * 512;
    const float* W1 = W + (size_t)(512 + j) * 512;
    const float* W2 = W + (size_t)(1024 + j) * 512;
    const float* W3 = W + (size_t)(1536 + j) * 512;

    for (int it = 0; it < 512; it++) {
        int t = grp ? (511 - it) : it;
        int pin = it & 1, pout = pin ^ 1;
        const float* h = g_hE[grp][pin];
        float a0 = 0, a1 = 0, a2 = 0, a3 = 0;
#pragma unroll
        for (int kk = 0; kk < 4; kk++) {
            int k = kk * 128 + lane * 4;
            float4 hv = ldcg4(h + k);
            a0 += dot4(*(const float4*)(W0 + k), hv);
            a1 += dot4(*(const float4*)(W1 + k), hv);
            a2 += dot4(*(const float4*)(W2 + k), hv);
            a3 += dot4(*(const float4*)(W3 + k), hv);
        }
        a0 = wredsum(a0); a1 = wredsum(a1); a2 = wredsum(a2); a3 = wredsum(a3);
        if (lane == 0) {
            const float* pre = g_pre + (size_t)t * 4096 + grp * 2048;
            float gi = a0 + pre[j];
            float gf = a1 + pre[512 + j];
            float gg = a2 + pre[1024 + j];
            float go = a3 + pre[1536 + j];
            float iv = sigm(gi), fv = sigm(gf), gv = tanhf(gg), ov = sigm(go);
            c = fv * c + iv * gv;
            float hn = ov * tanhf(c);
            g_hE[grp][pout][j] = hn;
            xs_next[(size_t)t * 1024 + grp * 512 + j] = hn;
            if (it == 511) {
                g_hdec[layer][0][grp * 512 + j] = hn;  // parity-0 = decoder init
                g_cdec[layer * 1024 + grp * 512 + j] = c;
            }
        }
        gsync(grp, 64);
    }
}

// ------------------------------ decoder LSTM cell phase --------------------
template <bool XCG>
DINL void dec_lstm_phase(const float* x, const float* h,
                         const float* __restrict__ wi, const float* __restrict__ wh,
                         const float* __restrict__ bb, int j, int lane,
                         float& c, float* hout) {
    const float* wi0 = wi + (size_t)(j) * 1024;
    const float* wi1 = wi + (size_t)(1024 + j) * 1024;
    const float* wi2 = wi + (size_t)(2048 + j) * 1024;
    const float* wi3 = wi + (size_t)(3072 + j) * 1024;
    const float* wh0 = wh + (size_t)(j) * 1024;
    const float* wh1 = wh + (size_t)(1024 + j) * 1024;
    const float* wh2 = wh + (size_t)(2048 + j) * 1024;
    const float* wh3 = wh + (size_t)(3072 + j) * 1024;
    float a0 = 0, a1 = 0, a2 = 0, a3 = 0;
#pragma unroll
    for (int kk = 0; kk < 8; kk++) {
        int k = kk * 128 + lane * 4;
        float4 xv = XCG ? ldcg4(x + k) : *(const float4*)(x + k);
        float4 hv = ldcg4(h + k);
        a0 += dot4(*(const float4*)(wi0 + k), xv) + dot4(*(const float4*)(wh0 + k), hv);
        a1 += dot4(*(const float4*)(wi1 + k), xv) + dot4(*(const float4*)(wh1 + k), hv);
        a2 += dot4(*(const float4*)(wi2 + k), xv) + dot4(*(const float4*)(wh2 + k), hv);
        a3 += dot4(*(const float4*)(wi3 + k), xv) + dot4(*(const float4*)(wh3 + k), hv);
    }
    a0 = wredsum(a0); a1 = wredsum(a1); a2 = wredsum(a2); a3 = wredsum(a3);
    if (lane == 0) {
        float gi = a0 + bb[j], gf = a1 + bb[1024 + j];
        float gg = a2 + bb[2048 + j], go = a3 + bb[3072 + j];
        float iv = sigm(gi), fv = sigm(gf), gv = tanhf(gg), ov = sigm(go);
        c = fv * c + iv * gv;
        hout[j] = ov * tanhf(c);
    }
}

// ------------------------------ decoder (persistent, 128 blocks x 512 thr) -
// Warps 0-7 of each block run the LSTM cells (j = blockIdx*8+wid, 1024 j's).
// All 16 warps (2048 total) run the classifier sweep with double-buffered
// prefetch (statically-indexed wA/wB registers -> no spills, 16 loads/warp
// in flight -> HBM-bound).
__global__ __launch_bounds__(512, 1) void decoder_kernel(
    const float* __restrict__ dec_emb, const float* __restrict__ Wih,
    const float* __restrict__ Whh, const float* __restrict__ bias,
    const float* __restrict__ clfW, const float* __restrict__ clfb) {
    int tid = threadIdx.x, lane = tid & 31, wid = tid >> 5;
    int j = blockIdx.x * 8 + wid;        // valid for wid < 8
    int gw2 = blockIdx.x * 16 + wid;     // 0..2047 classifier warp id
    __shared__ float sred[16];

    float c0 = 0.0f, c1 = 0.0f;
    if (wid < 8) {
        c0 = g_cdec[j];
        c1 = g_cdec[1024 + j];
    }
    unsigned tok = 1u;  // START_IDX

    const float* Wih1 = Wih + (size_t)4096 * 1024;
    const float* Whh1 = Whh + (size_t)4096 * 1024;
    const float* b0 = bias;
    const float* b1 = bias + 4096;

    for (int s = 0; s < 512; s++) {
        int pin = s & 1, pout = pin ^ 1;

        // ---- P1: layer 0  (x = embedding row) ----
        if (wid < 8)
            dec_lstm_phase<false>(dec_emb + (size_t)tok * 1024, g_hdec[0][pin],
                                  Wih, Whh, b0, j, lane, c0, g_hdec[0][pout]);
        gsync(2, 128);

        // ---- P2: layer 1  (x = h0 just written by other blocks -> ldcg) ----
        if (wid < 8)
            dec_lstm_phase<true>(g_hdec[0][pout], g_hdec[1][pin],
                                 Wih1, Whh1, b1, j, lane, c1, g_hdec[1][pout]);
        gsync(2, 128);

        // ---- P3: classifier logits + packed argmax (pipelined prefetch) ----
        {
            const float* h1 = g_hdec[1][pout];
            float4 hr[8];
#pragma unroll
            for (int kk = 0; kk < 8; kk++) hr[kk] = ldcg4(h1 + kk * 128 + lane * 4);
            unsigned long long best = 0ULL;
            const float* base = clfW + lane * 4;

            float4 wA[8], wB[8];
            {  // preload row gw2 into A
                const float* w = base + (size_t)gw2 * 1024;
#pragma unroll
                for (int kk = 0; kk < 8; kk++) wA[kk] = ldcs4(w + kk * 128);
            }
#pragma unroll 1
            for (int v = gw2; v < 32000; v += 4096) {
                int vB = v + 2048;
                {  // prefetch row vB into B (clamped if OOB)
                    const float* w = base + (size_t)(vB < 32000 ? vB : v) * 1024;
#pragma unroll
                    for (int kk = 0; kk < 8; kk++) wB[kk] = ldcs4(w + kk * 128);
                }
                float a = 0.0f;
#pragma unroll
                for (int kk = 0; kk < 8; kk++) a += dot4(wA[kk], hr[kk]);
                a = wredsum(a);
                if (lane == 0) {
                    a += clfb[v];
                    g_logits[v] = a;
                    unsigned u = __float_as_uint(a);
                    u = (u & 0x80000000u) ? ~u : (u | 0x80000000u);
                    unsigned long long p = ((unsigned long long)u << 32) |
                                           (unsigned long long)(0xFFFFFFFFu - (unsigned)v);
                    if (p > best) best = p;
                }
                int vA = v + 4096;
                {  // prefetch next A (clamped if OOB)
                    const float* w = base + (size_t)(vA < 32000 ? vA : v) * 1024;
#pragma unroll
                    for (int kk = 0; kk < 8; kk++) wA[kk] = ldcs4(w + kk * 128);
                }
                if (vB < 32000) {  // uniform per warp
                    float b = 0.0f;
#pragma unroll
                    for (int kk = 0; kk < 8; kk++) b += dot4(wB[kk], hr[kk]);
                    b = wredsum(b);
                    if (lane == 0) {
                        b += clfb[vB];
                        g_logits[vB] = b;
                        unsigned u = __float_as_uint(b);
                        u = (u & 0x80000000u) ? ~u : (u | 0x80000000u);
                        unsigned long long p = ((unsigned long long)u << 32) |
                                               (unsigned long long)(0xFFFFFFFFu - (unsigned)vB);
                        if (p > best) best = p;
                    }
                }
            }
            if (lane == 0) atomicMax(&g_packed[s], best);
        }
        gsync(2, 128);

        // ---- P4: exp / partial sums / next token (no barrier; next-step
        //      barriers cover the logits-overwrite hazard) ----
        {
            unsigned long long gp = *(volatile unsigned long long*)&g_packed[s];
            unsigned hu = (unsigned)(gp >> 32);
            float gmax = __uint_as_float((hu & 0x80000000u) ? (hu & 0x7FFFFFFFu) : ~hu);
            tok = 0xFFFFFFFFu - (unsigned)(gp & 0xFFFFFFFFu);

            float lsum = 0.0f;
            int gt = blockIdx.x * 512 + tid;  // 0..65535, single element each
            if (gt < 32000) {
                float e = __expf(__ldcg(&g_logits[gt]) - gmax);
                __stcs(&g_prob[(size_t)s * 32000 + gt], e);
                lsum = e;
            }
            lsum = wredsum(lsum);
            if (lane == 0) sred[wid] = lsum;
            __syncthreads();
            if (tid < 32) {
                float v2 = (lane < 16) ? sred[lane] : 0.0f;
                v2 += __shfl_xor_sync(0xFFFFFFFFu, v2, 8);
                v2 += __shfl_xor_sync(0xFFFFFFFFu, v2, 4);
                v2 += __shfl_xor_sync(0xFFFFFFFFu, v2, 2);
                v2 += __shfl_xor_sync(0xFFFFFFFFu, v2, 1);
                if (lane == 0) g_psum[s * 128 + blockIdx.x] = v2;
            }
        }
    }
}

// ------------------------------ deterministic softmax sums -----------------
__global__ void sums_kernel() {
    int s = blockIdx.x;
    int lane = threadIdx.x & 31, wid = threadIdx.x >> 5;
    float v = g_psum[s * 128 + threadIdx.x];
    v = wredsum(v);
    __shared__ float sr[4];
    if (lane == 0) sr[wid] = v;
    __syncthreads();
    if (threadIdx.x == 0) g_sums[s] = (sr[0] + sr[1]) + (sr[2] + sr[3]);
}

// ------------------------------ normalize + transpose to [V,T] -------------
__global__ void norm_tr_kernel(float* __restrict__ out) {
    __shared__ float tile[32][33];
    int v0 = blockIdx.x * 32, s0 = blockIdx.y * 32;
    int tx = threadIdx.x, ty = threadIdx.y;  // 32 x 8
#pragma unroll
    for (int i = 0; i < 32; i += 8)
        tile[ty + i][tx] = g_prob[(size_t)(s0 + ty + i) * 32000 + v0 + tx];
    __syncthreads();
    float rs = 1.0f / g_sums[s0 + tx];
#pragma unroll
    for (int i = 0; i < 32; i += 8)
        out[(size_t)(v0 + ty + i) * 512 + s0 + tx] = tile[tx][ty + i] * rs;
}

// ------------------------------ launch --------------------------------------
extern "C" void kernel_launch(void* const* d_in, const int* in_sizes, int n_in,
                              void* d_out, int out_size) {
    const int*   x       = (const int*)d_in[0];
    const float* enc_emb = (const float*)d_in[1];
    const float* enc_Wih = (const float*)d_in[2];
    const float* enc_Whh = (const float*)d_in[3];
    const float* enc_b   = (const float*)d_in[4];
    const float* dec_emb = (const float*)d_in[5];
    const float* dec_Wih = (const float*)d_in[6];
    const float* dec_Whh = (const float*)d_in[7];
    const float* dec_b   = (const float*)d_in[8];
    const float* clf_W   = (const float*)d_in[9];
    const float* clf_b   = (const float*)d_in[10];
    float* out = (float*)d_out;

    zero_kernel<<<1, 512>>>();
    embed_kernel<<<512, 256>>>(x, enc_emb);

    // encoder layer 0
    gemm_pre_kernel<<<dim3(32, 4), 256>>>(0, enc_Wih, enc_b);
    enc_rec_kernel<<<128, 256>>>(enc_Whh, 0);

    // encoder layer 1
    gemm_pre_kernel<<<dim3(32, 4), 256>>>(1, enc_Wih + (size_t)2 * 2048 * 1024,
                                          enc_b + 2 * 2048);
    enc_rec_kernel<<<128, 256>>>(enc_Whh + (size_t)2 * 2048 * 512, 1);

    // decoder (persistent, 512 greedy steps)
    decoder_kernel<<<128, 512>>>(dec_emb, dec_Wih, dec_Whh, dec_b, clf_W, clf_b);

    // softmax denominators + [V,T] output
    sums_kernel<<<512, 128>>>();
    norm_tr_kernel<<<dim3(1000, 16), dim3(32, 8)>>>(out);
}